// round 16
// baseline (speedup 1.0000x reference)
#include <cuda_runtime.h>
#include <cuda_fp16.h>
#include <cstdint>

#define TOK    32768
#define CDIM   256
#define KCODE  8192
#define BM     128
#define TAU    0.02f

// ---------------- scratch (device globals) ---------------------------------------
__device__ __half g_ch[KCODE * CDIM];   // negated codebook, fp16
__device__ float  g_cn[KCODE];          // 0.5 * ||e||^2 (fp64-accurate)
__device__ int    g_ind[TOK];
__device__ int    g_rlist[TOK];
__device__ int    g_nrescue;

// ---------------- kernel 0: no-op (aligns ncu -s 5 -c 1 onto the GEMM) -----------
__global__ void k_nop() {}

// ---------------- kernel 1: NCHW -> [T,C] transpose ------------------------------
__global__ void k_transpose(const float* __restrict__ in, float* __restrict__ data)
{
    __shared__ float tile[32][33];
    const int c0 = blockIdx.x * 32, h = blockIdx.y, n = blockIdx.z;
    {
        const int wx = threadIdx.x & 31, cy = threadIdx.x >> 5;
        #pragma unroll
        for (int i = 0; i < 4; i++) {
            const int c = cy + i * 8;
            tile[c][wx] = in[(((size_t)n * CDIM + c0 + c) * 32 + h) * 32 + wx];
        }
    }
    __syncthreads();
    {
        const int c = threadIdx.x & 31, wq = threadIdx.x >> 5;
        #pragma unroll
        for (int i = 0; i < 4; i++) {
            const int w = wq + i * 8;
            data[(size_t)(n * 1024 + h * 32 + w) * CDIM + c0 + c] = tile[c][w];
        }
    }
}

// ---------------- kernel 2: codebook prep ----------------------------------------
__global__ void k_codeprep(const float* __restrict__ cb)
{
    if (blockIdx.x == 0 && threadIdx.x == 0) g_nrescue = 0;
    const int warp = threadIdx.x >> 5, lane = threadIdx.x & 31;
    const int code = blockIdx.x * 8 + warp;
    const float* row = cb + (size_t)code * CDIM;
    double s = 0.0;
    #pragma unroll
    for (int i = 0; i < 8; i++) {
        const int c = lane + i * 32;
        const float e = row[c];
        s += (double)e * (double)e;
        g_ch[(size_t)code * CDIM + c] = __float2half_rn(-e);
    }
    #pragma unroll
    for (int o = 16; o > 0; o >>= 1) s += __shfl_xor_sync(0xffffffffu, s, o);
    if (lane == 0) g_cn[code] = (float)(0.5 * s);
}

// ---------------- helpers --------------------------------------------------------
__device__ __forceinline__ uint32_t smem_u32(const void* p) {
    uint32_t a;
    asm("{ .reg .u64 t; cvta.to.shared.u64 t, %1; cvt.u32.u64 %0, t; }" : "=r"(a) : "l"(p));
    return a;
}
__device__ __forceinline__ void cp16(uint32_t dst, const void* src) {
    asm volatile("cp.async.cg.shared.global [%0], [%1], 16;" :: "r"(dst), "l"(src) : "memory");
}
#define CP_COMMIT() asm volatile("cp.async.commit_group;" ::: "memory")
#define CP_WAIT1()  asm volatile("cp.async.wait_group 1;" ::: "memory")

__device__ __forceinline__ void ldsm4(uint32_t addr, uint32_t& r0, uint32_t& r1,
                                      uint32_t& r2, uint32_t& r3)
{
    asm volatile("ldmatrix.sync.aligned.m8n8.x4.shared.b16 {%0,%1,%2,%3}, [%4];"
                 : "=r"(r0), "=r"(r1), "=r"(r2), "=r"(r3) : "r"(addr));
}
__device__ __forceinline__ void mma16816(float* c, const uint32_t* a,
                                         uint32_t b0, uint32_t b1)
{
    asm volatile("mma.sync.aligned.m16n8k16.row.col.f32.f16.f16.f32 "
                 "{%0,%1,%2,%3}, {%4,%5,%6,%7}, {%8,%9}, {%0,%1,%2,%3};"
                 : "+f"(c[0]), "+f"(c[1]), "+f"(c[2]), "+f"(c[3])
                 : "r"(a[0]), "r"(a[1]), "r"(a[2]), "r"(a[3]), "r"(b0), "r"(b1));
}

// smem layout (bytes):
//   A  : 128 x 264 fp16 (pitch 528B) = 67584 @ 0
//   B  : 2 bufs x (128 codes x 72 fp16 pitch 144B = 18432) @ 67584
//   CN : 2 x 128 floats @ 104448
#define B_OFF     67584u
#define B_BUF     18432u
#define CN_OFF   104448u
#define SMEM_SZ  105472

// ---------------- kernel 3: fp16 GEMM + argmin, pipelined kk ---------------------
__global__ void __launch_bounds__(256, 2)
k_gemm_argmin(const float* __restrict__ data)
{
    extern __shared__ char smem[];
    const uint32_t sb = smem_u32(smem);
    const int tid = threadIdx.x, lane = tid & 31, warp = tid >> 5;
    const int mw = warp & 3;          // m-tile (32 rows each)
    const int ng = warp >> 2;         // n-group (64 codes each)
    const int blk = blockIdx.x;       // M tile (128 rows)

    // B slice cp.async addressing
    const int      g_off        = ((tid >> 3) * 32 + (tid & 7)) * 16;   // src bytes
    const uint32_t st_byte_base = (uint32_t)((tid >> 3) * 144 + (tid & 7) * 16);

    auto CP_SLICE = [&](int g) {
        const int chunk = g >> 2, s = g & 3;
        const char* src = (const char*)(g_ch + (size_t)chunk * 128 * CDIM + s * 64)
                        + g_off;
        const uint32_t dst = sb + B_OFF + (uint32_t)((g & 1) * B_BUF) + st_byte_base;
        #pragma unroll
        for (int i = 0; i < 4; i++) cp16(dst + i * 4608, src + i * 16384);
    };

    CP_SLICE(0); CP_COMMIT();
    CP_SLICE(1); CP_COMMIT();

    // ---- load A tile (fp32) and convert to fp16 in smem (overlaps cp flight) ----
    {
        const float4* src = (const float4*)(data + (size_t)blk * BM * CDIM);
        __half* Ah = (__half*)smem;
        #pragma unroll
        for (int i = 0; i < 32; i++) {
            const int u = tid + i * 256;
            const int row = u >> 6, c4 = u & 63;
            const float4 v = src[u];
            union { __half h[4]; uint2 q; } ph;
            ph.h[0] = __float2half_rn(v.x);
            ph.h[1] = __float2half_rn(v.y);
            ph.h[2] = __float2half_rn(v.z);
            ph.h[3] = __float2half_rn(v.w);
            *(uint2*)(Ah + row * 264 + c4 * 4) = ph.q;
        }
    }

    // ldmatrix per-thread bases
    const int a_row = mw * 32 + ((lane >> 3) & 1) * 8 + (lane & 7);
    const int a_c8  = (lane >> 4) * 8;
    const uint32_t aH_base = sb + (uint32_t)(a_row * 264 + a_c8) * 2u;
    const int b_row = (lane >> 4) * 8 + (lane & 7);
    const int b_c8  = ((lane >> 3) & 1) * 8;
    const uint32_t bT_base = sb + B_OFF
                           + (uint32_t)((ng * 64 + b_row) * 72 + b_c8) * 2u;

    float acc[2][8][4];                   // [m-tile][n8-tile][frag]
    float v1[2][2], v2[2][2];             // [m-tile][h]
    int   i1[2][2];
    #pragma unroll
    for (int mt = 0; mt < 2; mt++)
        #pragma unroll
        for (int h = 0; h < 2; h++) {
            v1[mt][h] = 3.4e38f; v2[mt][h] = 3.4e38f; i1[mt][h] = 0;
        }

    for (int g = 0; g < 256; ++g) {                  // 64 chunks x 4 k-slices
        const int chunk = g >> 2, s = g & 3;
        CP_WAIT1();                                  // slice g data landed
        __syncthreads();                             // ... and visible to all warps

        if (s == 0) {
            if (tid < 128)                           // stage chunk norms to smem
                *(float*)(smem + CN_OFF + (chunk & 1) * 512 + tid * 4)
                    = g_cn[chunk * 128 + tid];
            #pragma unroll
            for (int mt = 0; mt < 2; mt++)
                #pragma unroll
                for (int ct = 0; ct < 8; ++ct) {
                    acc[mt][ct][0] = 0.f; acc[mt][ct][1] = 0.f;
                    acc[mt][ct][2] = 0.f; acc[mt][ct][3] = 0.f;
                }
        }

        const uint32_t aH = aH_base + (uint32_t)(s * 128);
        const uint32_t bB = bT_base + (uint32_t)((g & 1) * B_BUF);

        // pipelined kk loop: B for kk+1 loads while mmas of kk run
        uint32_t bf[2][4][4];
        uint32_t af[2][4];
        ldsm4(aH,        af[0][0], af[0][1], af[0][2], af[0][3]);
        ldsm4(aH + 8448, af[1][0], af[1][1], af[1][2], af[1][3]);
        #pragma unroll
        for (int p = 0; p < 4; ++p)
            ldsm4(bB + (uint32_t)(p * 2304),
                  bf[0][p][0], bf[0][p][1], bf[0][p][2], bf[0][p][3]);

        #pragma unroll
        for (int kk = 0; kk < 4; ++kk) {
            const int cb = kk & 1, nb = cb ^ 1;
            if (kk < 3) {
                #pragma unroll
                for (int p = 0; p < 4; ++p)
                    ldsm4(bB + (uint32_t)(p * 2304 + (kk + 1) * 32),
                          bf[nb][p][0], bf[nb][p][1], bf[nb][p][2], bf[nb][p][3]);
            }
            #pragma unroll
            for (int p = 0; p < 4; ++p) {
                mma16816(acc[0][2 * p],     af[0], bf[cb][p][0], bf[cb][p][1]);
                mma16816(acc[0][2 * p + 1], af[0], bf[cb][p][2], bf[cb][p][3]);
                mma16816(acc[1][2 * p],     af[1], bf[cb][p][0], bf[cb][p][1]);
                mma16816(acc[1][2 * p + 1], af[1], bf[cb][p][2], bf[cb][p][3]);
            }
            if (kk < 3) {
                ldsm4(aH + (uint32_t)((kk + 1) * 32),
                      af[0][0], af[0][1], af[0][2], af[0][3]);
                ldsm4(aH + (uint32_t)(8448 + (kk + 1) * 32),
                      af[1][0], af[1][1], af[1][2], af[1][3]);
            }
        }

        if (s == 3) {        // chunk epilogue: score = 0.5||e||^2 - x.e, top-2
            const float* cns = (const float*)(smem + CN_OFF + (chunk & 1) * 512);
            #pragma unroll
            for (int mt = 0; mt < 2; mt++)
                #pragma unroll
                for (int ct = 0; ct < 8; ++ct) {
                    const int nl = ng * 64 + ct * 8 + (lane & 3) * 2;
                    const int nb = chunk * 128 + nl;
                    const float2 c2 = *(const float2*)(cns + nl);
                    const float sc[4] = { acc[mt][ct][0] + c2.x, acc[mt][ct][1] + c2.y,
                                          acc[mt][ct][2] + c2.x, acc[mt][ct][3] + c2.y };
                    #pragma unroll
                    for (int j = 0; j < 4; j++) {
                        const int h = j >> 1;
                        const float v = sc[j];
                        const int idx = nb + (j & 1);
                        if (v < v1[mt][h]) { v2[mt][h] = v1[mt][h]; v1[mt][h] = v; i1[mt][h] = idx; }
                        else if (v < v2[mt][h]) { v2[mt][h] = v; }
                    }
                }
        }

        // CRITICAL: all warps must be done reading buffer (g&1) before the
        // async prefetch of slice g+2 (which targets the SAME buffer) is issued.
        __syncthreads();
        if (g + 2 < 256) CP_SLICE(g + 2);
        CP_COMMIT();
    }

    // intra-warp top-2 reduce across the 4 lanes sharing each row
    float fa1[2][2], fa2[2][2]; int fai[2][2];
    #pragma unroll
    for (int mt = 0; mt < 2; mt++)
        #pragma unroll
        for (int h = 0; h < 2; ++h) {
            float a1 = v1[mt][h], a2 = v2[mt][h]; int ai = i1[mt][h];
            #pragma unroll
            for (int off = 1; off <= 2; off <<= 1) {
                const float o1 = __shfl_xor_sync(0xffffffffu, a1, off);
                const int   oi = __shfl_xor_sync(0xffffffffu, ai, off);
                const float o2 = __shfl_xor_sync(0xffffffffu, a2, off);
                if (o1 < a1 || (o1 == a1 && oi < ai)) {
                    a2 = fminf(a1, o2); a1 = o1; ai = oi;
                } else {
                    a2 = fminf(o1, a2);
                }
            }
            fa1[mt][h] = a1; fa2[mt][h] = a2; fai[mt][h] = ai;
        }

    // cross-n-group merge via smem (B region dead after main loop)
    float* mv1 = (float*)(smem + B_OFF);
    float* mv2 = (float*)(smem + B_OFF + 512);
    int*   mi  = (int*)  (smem + B_OFF + 1024);
    __syncthreads();
    if (ng == 1 && (lane & 3) == 0) {
        #pragma unroll
        for (int mt = 0; mt < 2; mt++)
            #pragma unroll
            for (int h = 0; h < 2; ++h) {
                const int r = mw * 32 + mt * 16 + h * 8 + (lane >> 2);
                mv1[r] = fa1[mt][h]; mv2[r] = fa2[mt][h]; mi[r] = fai[mt][h];
            }
    }
    __syncthreads();
    if (ng == 0 && (lane & 3) == 0) {
        #pragma unroll
        for (int mt = 0; mt < 2; mt++)
            #pragma unroll
            for (int h = 0; h < 2; ++h) {
                const int r = mw * 32 + mt * 16 + h * 8 + (lane >> 2);
                float a1 = fa1[mt][h], a2 = fa2[mt][h]; int ai = fai[mt][h];
                const float o1 = mv1[r], o2 = mv2[r]; const int oi = mi[r];
                if (o1 < a1 || (o1 == a1 && oi < ai)) {
                    a2 = fminf(a1, o2); a1 = o1; ai = oi;
                } else {
                    a2 = fminf(o1, a2);
                }
                const int row = blk * BM + r;
                g_ind[row] = ai;
                if (a2 - a1 < TAU) {
                    const int p = atomicAdd(&g_nrescue, 1);
                    if (p < TOK) g_rlist[p] = row;
                }
            }
    }
}

// ---------------- kernel 3.5: rescue — cheap scan + exact re-eval of near-best ---
__device__ __forceinline__ void macc(float& s, float& c, float a, float b)
{
    const float p  = __fmul_rn(a, b);
    const float pe = __fmaf_rn(a, b, -p);          // exact product tail
    const float t  = __fadd_rn(s, p);              // TwoSum(s, p)
    const float bb = __fsub_rn(t, s);
    const float er = __fadd_rn(__fsub_rn(s, __fsub_rn(t, bb)), __fsub_rn(p, bb));
    s = t;
    c = __fadd_rn(c, __fadd_rn(pe, er));
}

#define MAXCAND 128

__global__ void __launch_bounds__(256) k_rescue(const float* __restrict__ data,
                                                const float* __restrict__ cb)
{
    __shared__ float  xs[CDIM];
    __shared__ float  dap[KCODE];          // 32 KB approx distances
    __shared__ double ared[8];
    __shared__ float  wb[8];
    __shared__ int    cand[MAXCAND];
    __shared__ float  cex[MAXCAND];
    __shared__ int    ncand;
    const int tid = threadIdx.x, lane = tid & 31, warp = tid >> 5;
    int nr = g_nrescue; if (nr > TOK) nr = TOK;

    for (int it = blockIdx.x; it < nr; it += gridDim.x) {
        const int t = g_rlist[it];
        __syncthreads();
        xs[tid] = data[(size_t)t * CDIM + tid];
        if (tid == 0) ncand = 0;
        __syncthreads();

        // A = sum of fp32-rounded squares (fp64 accumulate, order-free)
        {
            double pa = (double)__fmul_rn(xs[tid], xs[tid]);
            #pragma unroll
            for (int o = 16; o > 0; o >>= 1) pa += __shfl_xor_sync(0xffffffffu, pa, o);
            if (lane == 0) ared[warp] = pa;
        }
        __syncthreads();
        double Ad = 0.0;
        #pragma unroll
        for (int w = 0; w < 8; w++) Ad += ared[w];
        const float Af = (float)Ad;

        float xa[8];
        #pragma unroll
        for (int j = 0; j < 8; j++) xa[j] = xs[lane * 8 + j];

        // Phase A: cheap scan (plain fp32), cache d_approx
        float best = 3.4e38f;
        for (int k = warp; k < KCODE; k += 8) {
            const float4* e4 = (const float4*)(cb + (size_t)k * CDIM) + lane * 2;
            const float4 b0 = e4[0], b1 = e4[1];
            float s0 = xa[0] * b0.x + xa[4] * b1.x;
            float s1 = xa[1] * b0.y + xa[5] * b1.y;
            float s2 = xa[2] * b0.z + xa[6] * b1.z;
            float s3 = xa[3] * b0.w + xa[7] * b1.w;
            float s = (s0 + s1) + (s2 + s3);
            #pragma unroll
            for (int o = 16; o > 0; o >>= 1) s += __shfl_xor_sync(0xffffffffu, s, o);
            const float d = (Af - 2.0f * s) + 2.0f * g_cn[k];
            if (lane == 0) dap[k] = d;
            best = fminf(best, d);
        }
        if (lane == 0) wb[warp] = best;
        __syncthreads();
        float gbest = wb[0];
        #pragma unroll
        for (int w = 1; w < 8; w++) gbest = fminf(gbest, wb[w]);

        // Phase B: collect near-best candidates
        const float thr = gbest + 1e-3f;
        for (int k = tid; k < KCODE; k += 256) {
            if (dap[k] < thr) {
                const int p = atomicAdd(&ncand, 1);
                if (p < MAXCAND) cand[p] = k;
            }
        }
        __syncthreads();
        int nc = ncand; if (nc > MAXCAND) nc = MAXCAND;

        // exact evaluation of candidates (one thread each)
        if (tid < nc) {
            const int k = cand[tid];
            const float* e = cb + (size_t)k * CDIM;
            float s = 0.f, c = 0.f;
            #pragma unroll 8
            for (int i = 0; i < CDIM; i++) macc(s, c, xs[i], e[i]);
            const float G = __fadd_rn(s, c);
            const float B = __fmul_rn(2.0f, G);
            const float C = __fmul_rn(2.0f, g_cn[k]);
            cex[tid] = __fadd_rn(__fsub_rn(Af, B), C);
        }
        __syncthreads();
        if (tid == 0) {
            float b = 3.4e38f; int bx = 0x7fffffff;
            for (int i = 0; i < nc; i++) {
                const float dv = cex[i]; const int ki = cand[i];
                if (dv < b || (dv == b && ki < bx)) { b = dv; bx = ki; }
            }
            g_ind[t] = bx;
        }
        __syncthreads();
    }
}

// ---------------- kernel 4: gather -> quantize + quantize_detach -----------------
__global__ void k_gather(const float* __restrict__ cb, float* __restrict__ out)
{
    const int id  = blockIdx.x * 256 + threadIdx.x;
    const int row = id >> 6, c4 = id & 63;
    const int ind = g_ind[row];
    const float4 v = ((const float4*)cb)[(size_t)ind * 64 + c4];
    float4* o4 = (float4*)out;
    o4[(size_t)row * 64 + c4] = v;
    o4[(size_t)TOK * 64 + (size_t)row * 64 + c4] = v;
}

// ---------------- launcher --------------------------------------------------------
extern "C" void kernel_launch(void* const* d_in, const int* in_sizes, int n_in,
                              void* d_out, int out_size)
{
    const float* input = (const float*)d_in[0];   // [32,256,32,32] fp32
    const float* cb    = (const float*)d_in[1];   // [8192,256] fp32
    float* out  = (float*)d_out;                  // [quantize | detach | data]
    float* data = out + (size_t)2 * TOK * CDIM;

    cudaFuncSetAttribute(k_gemm_argmin, cudaFuncAttributeMaxDynamicSharedMemorySize, SMEM_SZ);

    // harness issues 2 launches before ours; 1 nop puts k_gemm_argmin at index 5
    k_nop<<<1, 32>>>();
    k_transpose  <<<dim3(8, 32, 32), 256>>>(input, data);
    k_codeprep   <<<1024, 256>>>(cb);
    k_gemm_argmin<<<256, 256, SMEM_SZ>>>(data);
    k_rescue     <<<256, 256>>>(data, cb);
    k_gather     <<<8192, 256>>>(cb, out);
}

// round 17
// speedup vs baseline: 1.0309x; 1.0309x over previous
#include <cuda_runtime.h>
#include <cuda_fp16.h>
#include <cstdint>

#define TOK    32768
#define CDIM   256
#define KCODE  8192
#define BM     128
#define TAU    0.02f

// ---------------- scratch (device globals) ---------------------------------------
__device__ __half g_ch[KCODE * CDIM];   // negated codebook, fp16
__device__ float  g_cn[KCODE];          // 0.5 * ||e||^2 (fp64-accurate)
__device__ int    g_ind[TOK];
__device__ int    g_rlist[TOK];
__device__ int    g_nrescue;

// ---------------- kernel 0: no-op (aligns ncu -s 5 -c 1 onto the GEMM) -----------
__global__ void k_nop() {}

// ---------------- kernel 1: NCHW -> [T,C] transpose ------------------------------
__global__ void k_transpose(const float* __restrict__ in, float* __restrict__ data)
{
    __shared__ float tile[32][33];
    const int c0 = blockIdx.x * 32, h = blockIdx.y, n = blockIdx.z;
    {
        const int wx = threadIdx.x & 31, cy = threadIdx.x >> 5;
        #pragma unroll
        for (int i = 0; i < 4; i++) {
            const int c = cy + i * 8;
            tile[c][wx] = in[(((size_t)n * CDIM + c0 + c) * 32 + h) * 32 + wx];
        }
    }
    __syncthreads();
    {
        const int c = threadIdx.x & 31, wq = threadIdx.x >> 5;
        #pragma unroll
        for (int i = 0; i < 4; i++) {
            const int w = wq + i * 8;
            data[(size_t)(n * 1024 + h * 32 + w) * CDIM + c0 + c] = tile[c][w];
        }
    }
}

// ---------------- kernel 2: codebook prep ----------------------------------------
__global__ void k_codeprep(const float* __restrict__ cb)
{
    if (blockIdx.x == 0 && threadIdx.x == 0) g_nrescue = 0;
    const int warp = threadIdx.x >> 5, lane = threadIdx.x & 31;
    const int code = blockIdx.x * 8 + warp;
    const float* row = cb + (size_t)code * CDIM;
    double s = 0.0;
    #pragma unroll
    for (int i = 0; i < 8; i++) {
        const int c = lane + i * 32;
        const float e = row[c];
        s += (double)e * (double)e;
        g_ch[(size_t)code * CDIM + c] = __float2half_rn(-e);
    }
    #pragma unroll
    for (int o = 16; o > 0; o >>= 1) s += __shfl_xor_sync(0xffffffffu, s, o);
    if (lane == 0) g_cn[code] = (float)(0.5 * s);
}

// ---------------- helpers --------------------------------------------------------
__device__ __forceinline__ uint32_t smem_u32(const void* p) {
    uint32_t a;
    asm("{ .reg .u64 t; cvta.to.shared.u64 t, %1; cvt.u32.u64 %0, t; }" : "=r"(a) : "l"(p));
    return a;
}
__device__ __forceinline__ void cp16(uint32_t dst, const void* src) {
    asm volatile("cp.async.cg.shared.global [%0], [%1], 16;" :: "r"(dst), "l"(src) : "memory");
}
#define CP_COMMIT() asm volatile("cp.async.commit_group;" ::: "memory")
#define CP_WAIT1()  asm volatile("cp.async.wait_group 1;" ::: "memory")

__device__ __forceinline__ void ldsm4(uint32_t addr, uint32_t& r0, uint32_t& r1,
                                      uint32_t& r2, uint32_t& r3)
{
    asm volatile("ldmatrix.sync.aligned.m8n8.x4.shared.b16 {%0,%1,%2,%3}, [%4];"
                 : "=r"(r0), "=r"(r1), "=r"(r2), "=r"(r3) : "r"(addr));
}
__device__ __forceinline__ void mma16816(float* c, const uint32_t* a,
                                         uint32_t b0, uint32_t b1)
{
    asm volatile("mma.sync.aligned.m16n8k16.row.col.f32.f16.f16.f32 "
                 "{%0,%1,%2,%3}, {%4,%5,%6,%7}, {%8,%9}, {%0,%1,%2,%3};"
                 : "+f"(c[0]), "+f"(c[1]), "+f"(c[2]), "+f"(c[3])
                 : "r"(a[0]), "r"(a[1]), "r"(a[2]), "r"(a[3]), "r"(b0), "r"(b1));
}

// smem layout (bytes):
//   A  : 128 x 264 fp16 (pitch 528B) = 67584 @ 0
//   B  : 2 bufs x (128 codes x 72 fp16 pitch 144B = 18432) @ 67584
//   CN : 2 x 128 floats @ 104448
#define B_OFF     67584u
#define B_BUF     18432u
#define CN_OFF   104448u
#define SMEM_SZ  105472

// ---------------- kernel 3: fp16 GEMM + argmin, pipelined kk ---------------------
__global__ void __launch_bounds__(256, 2)
k_gemm_argmin(const float* __restrict__ data)
{
    extern __shared__ char smem[];
    const uint32_t sb = smem_u32(smem);
    const int tid = threadIdx.x, lane = tid & 31, warp = tid >> 5;
    const int mw = warp & 3;          // m-tile (32 rows each)
    const int ng = warp >> 2;         // n-group (64 codes each)
    const int blk = blockIdx.x;       // M tile (128 rows)

    // B slice cp.async addressing
    const int      g_off        = ((tid >> 3) * 32 + (tid & 7)) * 16;   // src bytes
    const uint32_t st_byte_base = (uint32_t)((tid >> 3) * 144 + (tid & 7) * 16);

    auto CP_SLICE = [&](int g) {
        const int chunk = g >> 2, s = g & 3;
        const char* src = (const char*)(g_ch + (size_t)chunk * 128 * CDIM + s * 64)
                        + g_off;
        const uint32_t dst = sb + B_OFF + (uint32_t)((g & 1) * B_BUF) + st_byte_base;
        #pragma unroll
        for (int i = 0; i < 4; i++) cp16(dst + i * 4608, src + i * 16384);
    };

    CP_SLICE(0); CP_COMMIT();
    CP_SLICE(1); CP_COMMIT();

    // ---- load A tile (fp32) and convert to fp16 in smem (overlaps cp flight) ----
    {
        const float4* src = (const float4*)(data + (size_t)blk * BM * CDIM);
        __half* Ah = (__half*)smem;
        #pragma unroll
        for (int i = 0; i < 32; i++) {
            const int u = tid + i * 256;
            const int row = u >> 6, c4 = u & 63;
            const float4 v = src[u];
            union { __half h[4]; uint2 q; } ph;
            ph.h[0] = __float2half_rn(v.x);
            ph.h[1] = __float2half_rn(v.y);
            ph.h[2] = __float2half_rn(v.z);
            ph.h[3] = __float2half_rn(v.w);
            *(uint2*)(Ah + row * 264 + c4 * 4) = ph.q;
        }
    }

    // ldmatrix per-thread bases
    const int a_row = mw * 32 + ((lane >> 3) & 1) * 8 + (lane & 7);
    const int a_c8  = (lane >> 4) * 8;
    const uint32_t aH_base = sb + (uint32_t)(a_row * 264 + a_c8) * 2u;
    const int b_row = (lane >> 4) * 8 + (lane & 7);
    const int b_c8  = ((lane >> 3) & 1) * 8;
    const uint32_t bT_base = sb + B_OFF
                           + (uint32_t)((ng * 64 + b_row) * 72 + b_c8) * 2u;

    float acc[2][8][4];                   // [m-tile][n8-tile][frag]
    float v1[2][2], v2[2][2];             // [m-tile][h]
    int   i1[2][2];
    #pragma unroll
    for (int mt = 0; mt < 2; mt++)
        #pragma unroll
        for (int h = 0; h < 2; h++) {
            v1[mt][h] = 3.4e38f; v2[mt][h] = 3.4e38f; i1[mt][h] = 0;
        }

    for (int g = 0; g < 256; ++g) {                  // 64 chunks x 4 k-slices
        const int chunk = g >> 2, s = g & 3;
        CP_WAIT1();                                  // slice g data landed
        __syncthreads();                             // ... and visible to all warps

        if (s == 0) {
            if (tid < 128)                           // stage chunk norms to smem
                *(float*)(smem + CN_OFF + (chunk & 1) * 512 + tid * 4)
                    = g_cn[chunk * 128 + tid];
            #pragma unroll
            for (int mt = 0; mt < 2; mt++)
                #pragma unroll
                for (int ct = 0; ct < 8; ++ct) {
                    acc[mt][ct][0] = 0.f; acc[mt][ct][1] = 0.f;
                    acc[mt][ct][2] = 0.f; acc[mt][ct][3] = 0.f;
                }
        }

        const uint32_t aH = aH_base + (uint32_t)(s * 128);
        const uint32_t bB = bT_base + (uint32_t)((g & 1) * B_BUF);

        // pipelined kk loop: B for kk+1 loads while mmas of kk run
        uint32_t bf[2][4][4];
        uint32_t af[2][4];
        ldsm4(aH,        af[0][0], af[0][1], af[0][2], af[0][3]);
        ldsm4(aH + 8448, af[1][0], af[1][1], af[1][2], af[1][3]);
        #pragma unroll
        for (int p = 0; p < 4; ++p)
            ldsm4(bB + (uint32_t)(p * 2304),
                  bf[0][p][0], bf[0][p][1], bf[0][p][2], bf[0][p][3]);

        #pragma unroll
        for (int kk = 0; kk < 4; ++kk) {
            const int cb = kk & 1, nb = cb ^ 1;
            if (kk < 3) {
                #pragma unroll
                for (int p = 0; p < 4; ++p)
                    ldsm4(bB + (uint32_t)(p * 2304 + (kk + 1) * 32),
                          bf[nb][p][0], bf[nb][p][1], bf[nb][p][2], bf[nb][p][3]);
            }
            #pragma unroll
            for (int p = 0; p < 4; ++p) {
                mma16816(acc[0][2 * p],     af[0], bf[cb][p][0], bf[cb][p][1]);
                mma16816(acc[0][2 * p + 1], af[0], bf[cb][p][2], bf[cb][p][3]);
                mma16816(acc[1][2 * p],     af[1], bf[cb][p][0], bf[cb][p][1]);
                mma16816(acc[1][2 * p + 1], af[1], bf[cb][p][2], bf[cb][p][3]);
            }
            if (kk < 3) {
                ldsm4(aH + (uint32_t)((kk + 1) * 32),
                      af[0][0], af[0][1], af[0][2], af[0][3]);
                ldsm4(aH + (uint32_t)(8448 + (kk + 1) * 32),
                      af[1][0], af[1][1], af[1][2], af[1][3]);
            }
        }

        // all warps done reading buffer (g&1): issue its refill EARLY so the
        // async copy overlaps the epilogue below (numerics unaffected).
        __syncthreads();
        if (g + 2 < 256) CP_SLICE(g + 2);
        CP_COMMIT();

        if (s == 3) {        // chunk epilogue: score = 0.5||e||^2 - x.e, top-2
            const float* cns = (const float*)(smem + CN_OFF + (chunk & 1) * 512);
            #pragma unroll
            for (int mt = 0; mt < 2; mt++)
                #pragma unroll
                for (int ct = 0; ct < 8; ++ct) {
                    const int nl = ng * 64 + ct * 8 + (lane & 3) * 2;
                    const int nb = chunk * 128 + nl;
                    const float2 c2 = *(const float2*)(cns + nl);
                    const float sc[4] = { acc[mt][ct][0] + c2.x, acc[mt][ct][1] + c2.y,
                                          acc[mt][ct][2] + c2.x, acc[mt][ct][3] + c2.y };
                    #pragma unroll
                    for (int j = 0; j < 4; j++) {
                        const int h = j >> 1;
                        const float v = sc[j];
                        const int idx = nb + (j & 1);
                        if (v < v1[mt][h]) { v2[mt][h] = v1[mt][h]; v1[mt][h] = v; i1[mt][h] = idx; }
                        else if (v < v2[mt][h]) { v2[mt][h] = v; }
                    }
                }
        }
    }

    // intra-warp top-2 reduce across the 4 lanes sharing each row
    float fa1[2][2], fa2[2][2]; int fai[2][2];
    #pragma unroll
    for (int mt = 0; mt < 2; mt++)
        #pragma unroll
        for (int h = 0; h < 2; ++h) {
            float a1 = v1[mt][h], a2 = v2[mt][h]; int ai = i1[mt][h];
            #pragma unroll
            for (int off = 1; off <= 2; off <<= 1) {
                const float o1 = __shfl_xor_sync(0xffffffffu, a1, off);
                const int   oi = __shfl_xor_sync(0xffffffffu, ai, off);
                const float o2 = __shfl_xor_sync(0xffffffffu, a2, off);
                if (o1 < a1 || (o1 == a1 && oi < ai)) {
                    a2 = fminf(a1, o2); a1 = o1; ai = oi;
                } else {
                    a2 = fminf(o1, a2);
                }
            }
            fa1[mt][h] = a1; fa2[mt][h] = a2; fai[mt][h] = ai;
        }

    // cross-n-group merge via smem (B region dead after main loop)
    float* mv1 = (float*)(smem + B_OFF);
    float* mv2 = (float*)(smem + B_OFF + 512);
    int*   mi  = (int*)  (smem + B_OFF + 1024);
    __syncthreads();
    if (ng == 1 && (lane & 3) == 0) {
        #pragma unroll
        for (int mt = 0; mt < 2; mt++)
            #pragma unroll
            for (int h = 0; h < 2; ++h) {
                const int r = mw * 32 + mt * 16 + h * 8 + (lane >> 2);
                mv1[r] = fa1[mt][h]; mv2[r] = fa2[mt][h]; mi[r] = fai[mt][h];
            }
    }
    __syncthreads();
    if (ng == 0 && (lane & 3) == 0) {
        #pragma unroll
        for (int mt = 0; mt < 2; mt++)
            #pragma unroll
            for (int h = 0; h < 2; ++h) {
                const int r = mw * 32 + mt * 16 + h * 8 + (lane >> 2);
                float a1 = fa1[mt][h], a2 = fa2[mt][h]; int ai = fai[mt][h];
                const float o1 = mv1[r], o2 = mv2[r]; const int oi = mi[r];
                if (o1 < a1 || (o1 == a1 && oi < ai)) {
                    a2 = fminf(a1, o2); a1 = o1; ai = oi;
                } else {
                    a2 = fminf(o1, a2);
                }
                const int row = blk * BM + r;
                g_ind[row] = ai;
                if (a2 - a1 < TAU) {
                    const int p = atomicAdd(&g_nrescue, 1);
                    if (p < TOK) g_rlist[p] = row;
                }
            }
    }
}

// ---------------- kernel 3.5: rescue — fp16 cheap scan + exact re-eval -----------
__device__ __forceinline__ void macc(float& s, float& c, float a, float b)
{
    const float p  = __fmul_rn(a, b);
    const float pe = __fmaf_rn(a, b, -p);          // exact product tail
    const float t  = __fadd_rn(s, p);              // TwoSum(s, p)
    const float bb = __fsub_rn(t, s);
    const float er = __fadd_rn(__fsub_rn(s, __fsub_rn(t, bb)), __fsub_rn(p, bb));
    s = t;
    c = __fadd_rn(c, __fadd_rn(pe, er));
}

#define MAXCAND 256

__global__ void __launch_bounds__(256) k_rescue(const float* __restrict__ data,
                                                const float* __restrict__ cb)
{
    __shared__ float  xs[CDIM];
    __shared__ float  dap[KCODE];          // 32 KB approx distances
    __shared__ double ared[8];
    __shared__ float  wb[8];
    __shared__ int    wbi[8];
    __shared__ int    cand[MAXCAND];
    __shared__ float  cex[MAXCAND];
    __shared__ int    ncand;
    const int tid = threadIdx.x, lane = tid & 31, warp = tid >> 5;
    int nr = g_nrescue; if (nr > TOK) nr = TOK;

    for (int it = blockIdx.x; it < nr; it += gridDim.x) {
        const int t = g_rlist[it];
        __syncthreads();
        xs[tid] = data[(size_t)t * CDIM + tid];
        if (tid == 0) ncand = 0;
        __syncthreads();

        // A = sum of fp32-rounded squares (fp64 accumulate, order-free)
        {
            double pa = (double)__fmul_rn(xs[tid], xs[tid]);
            #pragma unroll
            for (int o = 16; o > 0; o >>= 1) pa += __shfl_xor_sync(0xffffffffu, pa, o);
            if (lane == 0) ared[warp] = pa;
        }
        __syncthreads();
        double Ad = 0.0;
        #pragma unroll
        for (int w = 0; w < 8; w++) Ad += ared[w];
        const float Af = (float)Ad;

        float xa[8];
        #pragma unroll
        for (int j = 0; j < 8; j++) xa[j] = xs[lane * 8 + j];

        // Phase A: cheap scan over fp16 NEGATED codebook (half the L2 traffic)
        float best = 3.4e38f;
        for (int k = warp; k < KCODE; k += 8) {
            const uint4 bv4 = *((const uint4*)(g_ch + (size_t)k * CDIM) + lane);
            const __half2* h2 = (const __half2*)&bv4;
            const float2 f0 = __half22float2(h2[0]);
            const float2 f1 = __half22float2(h2[1]);
            const float2 f2 = __half22float2(h2[2]);
            const float2 f3 = __half22float2(h2[3]);
            float s = xa[0] * f0.x + xa[1] * f0.y + xa[2] * f1.x + xa[3] * f1.y
                    + xa[4] * f2.x + xa[5] * f2.y + xa[6] * f3.x + xa[7] * f3.y;
            #pragma unroll
            for (int o = 16; o > 0; o >>= 1) s += __shfl_xor_sync(0xffffffffu, s, o);
            const float d = (Af + 2.0f * s) + 2.0f * g_cn[k];   // s ~= -x.e
            if (lane == 0) dap[k] = d;
            best = fminf(best, d);
        }
        if (lane == 0) wb[warp] = best;
        __syncthreads();
        float gbest = wb[0];
        #pragma unroll
        for (int w = 1; w < 8; w++) gbest = fminf(gbest, wb[w]);

        // Phase B: collect near-best candidates (window covers fp16 scan noise)
        const float thr = gbest + 0.06f;
        for (int k = tid; k < KCODE; k += 256) {
            if (dap[k] < thr) {
                const int p = atomicAdd(&ncand, 1);
                if (p < MAXCAND) cand[p] = k;
            }
        }
        __syncthreads();
        const int nc = ncand;

        if (nc <= MAXCAND) {
            // exact evaluation of candidates (one thread each)
            if (tid < nc) {
                const int k = cand[tid];
                const float* e = cb + (size_t)k * CDIM;
                float s = 0.f, c = 0.f;
                #pragma unroll 8
                for (int i = 0; i < CDIM; i++) macc(s, c, xs[i], e[i]);
                const float G = __fadd_rn(s, c);
                const float B = __fmul_rn(2.0f, G);
                const float C = __fmul_rn(2.0f, g_cn[k]);
                cex[tid] = __fadd_rn(__fsub_rn(Af, B), C);
            }
            __syncthreads();
            if (tid == 0) {
                float b = 3.4e38f; int bx = 0x7fffffff;
                for (int i = 0; i < nc; i++) {
                    const float dv = cex[i]; const int ki = cand[i];
                    if (dv < b || (dv == b && ki < bx)) { b = dv; bx = ki; }
                }
                g_ind[t] = bx;
            }
        } else {
            // fallback: exact compensated warp-per-code scan of ALL codes
            float fb = 3.4e38f; int fbi = 0x7fffffff;
            for (int k = warp; k < KCODE; k += 8) {
                const float4* e4 = (const float4*)(cb + (size_t)k * CDIM) + lane * 2;
                const float4 b0 = e4[0], b1 = e4[1];
                float s = 0.f, c = 0.f;
                macc(s, c, xa[0], b0.x); macc(s, c, xa[1], b0.y);
                macc(s, c, xa[2], b0.z); macc(s, c, xa[3], b0.w);
                macc(s, c, xa[4], b1.x); macc(s, c, xa[5], b1.y);
                macc(s, c, xa[6], b1.z); macc(s, c, xa[7], b1.w);
                #pragma unroll
                for (int o = 16; o > 0; o >>= 1) {
                    const float so = __shfl_xor_sync(0xffffffffu, s, o);
                    const float co = __shfl_xor_sync(0xffffffffu, c, o);
                    const float tt = __fadd_rn(s, so);
                    const float bb = __fsub_rn(tt, s);
                    const float er = __fadd_rn(__fsub_rn(s, __fsub_rn(tt, bb)),
                                               __fsub_rn(so, bb));
                    s = tt;
                    c = __fadd_rn(c, __fadd_rn(co, er));
                }
                const float G = __fadd_rn(s, c);
                const float d = __fadd_rn(__fsub_rn(Af, __fmul_rn(2.0f, G)),
                                          __fmul_rn(2.0f, g_cn[k]));
                if (d < fb || (d == fb && k < fbi)) { fb = d; fbi = k; }
            }
            if (lane == 0) { wb[warp] = fb; wbi[warp] = fbi; }
            __syncthreads();
            if (tid == 0) {
                float b = wb[0]; int bx = wbi[0];
                #pragma unroll
                for (int w = 1; w < 8; w++)
                    if (wb[w] < b || (wb[w] == b && wbi[w] < bx)) { b = wb[w]; bx = wbi[w]; }
                g_ind[t] = bx;
            }
        }
        __syncthreads();
    }
}

// ---------------- kernel 4: gather -> quantize + quantize_detach -----------------
__global__ void k_gather(const float* __restrict__ cb, float* __restrict__ out)
{
    const int id  = blockIdx.x * 256 + threadIdx.x;
    const int row = id >> 6, c4 = id & 63;
    const int ind = g_ind[row];
    const float4 v = ((const float4*)cb)[(size_t)ind * 64 + c4];
    float4* o4 = (float4*)out;
    o4[(size_t)row * 64 + c4] = v;
    o4[(size_t)TOK * 64 + (size_t)row * 64 + c4] = v;
}

// ---------------- launcher --------------------------------------------------------
extern "C" void kernel_launch(void* const* d_in, const int* in_sizes, int n_in,
                              void* d_out, int out_size)
{
    const float* input = (const float*)d_in[0];   // [32,256,32,32] fp32
    const float* cb    = (const float*)d_in[1];   // [8192,256] fp32
    float* out  = (float*)d_out;                  // [quantize | detach | data]
    float* data = out + (size_t)2 * TOK * CDIM;

    cudaFuncSetAttribute(k_gemm_argmin, cudaFuncAttributeMaxDynamicSharedMemorySize, SMEM_SZ);

    // harness issues 2 launches before ours; 1 nop puts k_gemm_argmin at index 5
    k_nop<<<1, 32>>>();
    k_transpose  <<<dim3(8, 32, 32), 256>>>(input, data);
    k_codeprep   <<<1024, 256>>>(cb);
    k_gemm_argmin<<<256, 256, SMEM_SZ>>>(data);
    k_rescue     <<<256, 256>>>(data, cb);
    k_gather     <<<8192, 256>>>(cb, out);
}